// round 6
// baseline (speedup 1.0000x reference)
#include <cuda_runtime.h>
#include <cuda_bf16.h>
#include <math.h>

// ---------------- constants ----------------
#define NSPEC 5456
#define PI_F 3.14159265358979323846f

__constant__ int c_OFF[17] = {0,1,10,35,84,165,286,455,680,969,1330,1771,2300,2925,3654,4495,5456};

// ---------------- scratch (static device globals; no allocation) ----------------
__device__ float2 g_T1[8388608];     // [bf=128][m=16][j=64][c=64]   (m >= 0 only)
__device__ float2 g_T2[7872512];     // [bf=128][mi=31][ni=31][j=64]
__device__ float  g_Wan[NSPEC*64];   // wigner(beta_in) * quad weight
__device__ float  g_Wsy[NSPEC*32];   // wigner(beta_out) * (2l+1)
__device__ float2 g_D[NSPEC*72];     // wigner(beta_g) * exp(-i(m a + n g))
__device__ float  g_wquad[64];
__device__ float  g_KT[72*512];      // kernel^T * SCALING : [g][i*32+o]
__device__ float2 g_xc[NSPEC*128];   // [s][b*16+f]
__device__ float2 g_yc[NSPEC*512];   // [s][i*32+o]
__device__ float2 g_zc[NSPEC*256];   // [s][b*32+o]
__device__ float2 g_Zsum[7872512];   // [mi=31][ni=31][j=32][bo=256]
__device__ float2 g_U1[8126464];     // [a=32][ni=31][j=32][bo=256]

// ---------------- init: quadrature weights + transposed scaled kernel ----------------
__global__ void k_init(const float* __restrict__ ker) {
    int idx = blockIdx.x * blockDim.x + threadIdx.x;
    if (idx < 36864) {
        int g  = idx >> 9;     // 0..71
        int io = idx & 511;    // i*32+o
        g_KT[idx] = ker[io * 72 + g] * (1.0f / 12.0f);   // SCALING = 1/12
    }
    if (idx < 64) {
        int j = idx;
        float inner = 0.0f;
        for (int k = 0; k < 32; k++)
            inner += sinf((float)((2*j+1)*(2*k+1)) * PI_F / 128.0f) / (float)(2*k+1);
        float w = (2.0f / 32.0f) * sinf(PI_F * (float)(2*j+1) / 128.0f) * inner;
        g_wquad[j] = w / 4096.0f;
    }
}

// ---------------- Wigner tables (one block per spectral index) ----------------
__global__ void k_wigner(const float* __restrict__ ge) {
    int s = blockIdx.x;
    __shared__ float lcoef[32];
    __shared__ int shp[5];   // l, M, N, Kmin, Kmax
    if (threadIdx.x == 0) {
        int l = 0; while (c_OFF[l+1] <= s) l++;
        int dsz = 2*l + 1;
        int rem = s - c_OFF[l];
        int M = rem / dsz - l;
        int N = rem % dsz - l;
        int Kmin = (M - N) > 0 ? (M - N) : 0;
        int Kmax = (l + M) < (l - N) ? (l + M) : (l - N);
        double lf[32];
        lf[0] = 0.0;
        for (int i = 1; i < 32; i++) lf[i] = lf[i-1] + log((double)i);
        double lgA = 0.5 * (lf[l+M] + lf[l-M] + lf[l+N] + lf[l-N]);
        for (int K = Kmin; K <= Kmax; K++)
            lcoef[K] = (float)(lgA - (lf[K] + lf[l+M-K] + lf[l-N-K] + lf[N-M+K]));
        shp[0] = l; shp[1] = M; shp[2] = N; shp[3] = Kmin; shp[4] = Kmax;
    }
    __syncthreads();
    int t = threadIdx.x;
    if (t >= 168) return;
    int l = shp[0], M = shp[1], N = shp[2], Kmin = shp[3], Kmax = shp[4];
    float beta;
    if (t < 64)       beta = PI_F * (float)(2*t + 1) / 128.0f;         // beta_in  (4*B_IN=128)
    else if (t < 96)  beta = PI_F * (float)(2*(t-64) + 1) / 64.0f;     // beta_out (4*B_OUT=64)
    else              beta = ge[(t - 96) * 3 + 1];                     // grid beta
    float ch  = cosf(0.5f * beta);
    float shv = sinf(0.5f * beta);
    float lc  = logf(ch);
    float lsn = logf(shv);
    float dval = 0.0f;
    for (int K = Kmin; K <= Kmax; K++) {
        int e1 = 2*l + M - N - 2*K;
        int e2 = N - M + 2*K;
        float arg = lcoef[K];
        if (e1) arg += (float)e1 * lc;
        if (e2) arg += (float)e2 * lsn;
        float term = expf(arg);
        dval += (K & 1) ? -term : term;
    }
    if (t < 64) {
        g_Wan[s * 64 + t] = dval * g_wquad[t];
    } else if (t < 96) {
        g_Wsy[s * 32 + (t - 64)] = dval * (float)(2*l + 1);
    } else {
        int g = t - 96;
        float alpha = ge[g*3 + 0], gamma = ge[g*3 + 2];
        float th = (float)M * alpha + (float)N * gamma;
        float sv, cv; sincosf(th, &sv, &cv);
        g_D[s * 72 + g] = make_float2(dval * cv, -dval * sv);
    }
}

// ---------------- Stage A: DFT over first spatial axis (real input, m=0..15) ----------------
// block per (bf, j): 8192 blocks x 256 threads
__global__ void k_dftA(const float* __restrict__ x) {
    __shared__ float  sx[4096];    // [a=64][c=64]
    __shared__ float2 stw[1024];   // [m=16][a=64]  e^{-2*pi*i*a*m/64}
    int bid = blockIdx.x;
    int j = bid & 63, bf = bid >> 6;
    int tid = threadIdx.x;
    for (int idx = tid; idx < 4096; idx += 256) {
        int a = idx >> 6, c = idx & 63;
        sx[idx] = x[bf * 262144 + a * 4096 + j * 64 + c];
    }
    for (int idx = tid; idx < 1024; idx += 256) {
        int m = idx >> 6, a = idx & 63;
        float ang = 0.0981747704f * (float)(a * m);   // pi/32 * a * m
        float sv, cv; sincosf(ang, &sv, &cv);
        stw[idx] = make_float2(cv, -sv);
    }
    __syncthreads();
    for (int o = tid; o < 1024; o += 256) {
        int m = o >> 6, c = o & 63;
        float ax = 0.0f, ay = 0.0f;
        #pragma unroll 8
        for (int a = 0; a < 64; a++) {
            float xv = sx[a * 64 + c];
            float2 tw = stw[m * 64 + a];
            ax += xv * tw.x;
            ay += xv * tw.y;
        }
        g_T1[bf * 65536 + m * 4096 + j * 64 + c] = make_float2(ax, ay);
    }
}

// ---------------- Stage C: DFT over third spatial axis ----------------
// block per (bf, mi): 3968 blocks x 256 threads
__global__ void k_dftC() {
    __shared__ float2 sT[4096];    // [j=64][c=64]
    __shared__ float2 twn[1984];   // [ni=31][c=64]  e^{-2*pi*i*c*n/64}
    int bid = blockIdx.x;
    int bf = bid / 31, mi = bid % 31;
    int m = mi - 15;
    int am = m < 0 ? -m : m;
    int tid = threadIdx.x;
    for (int idx = tid; idx < 4096; idx += 256) {
        float2 v = g_T1[bf * 65536 + am * 4096 + idx];
        if (m < 0) v.y = -v.y;                // conj symmetry (real input)
        sT[idx] = v;
    }
    for (int idx = tid; idx < 1984; idx += 256) {
        int ni = idx >> 6, c = idx & 63;
        float ang = 0.0981747704f * (float)(c * (ni - 15));
        float sv, cv; sincosf(ang, &sv, &cv);
        twn[idx] = make_float2(cv, -sv);
    }
    __syncthreads();
    for (int o = tid; o < 1984; o += 256) {
        int ni = o >> 6, j = o & 63;
        float ax = 0.0f, ay = 0.0f;
        #pragma unroll 8
        for (int c = 0; c < 64; c++) {
            float2 a = sT[j * 64 + c];
            float2 t = twn[ni * 64 + c];
            ax += a.x * t.x - a.y * t.y;
            ay += a.x * t.y + a.y * t.x;
        }
        g_T2[(bf * 31 + mi) * 1984 + ni * 64 + j] = make_float2(ax, ay);
    }
}

// ---------------- xc[s][bf] = sum_j T2[bf][m][n][j] * Wan[s][j] ----------------
// block per s: 5456 blocks x 128 threads
__global__ void k_xc() {
    int s = blockIdx.x;
    __shared__ float wan[64];
    __shared__ int shp[2];
    if (threadIdx.x == 0) {
        int l = 0; while (c_OFF[l+1] <= s) l++;
        int dsz = 2*l + 1;
        int rem = s - c_OFF[l];
        shp[0] = rem / dsz - l + 15;   // mi
        shp[1] = rem % dsz - l + 15;   // ni
    }
    if (threadIdx.x < 64) wan[threadIdx.x] = g_Wan[s * 64 + threadIdx.x];
    __syncthreads();
    int bf = threadIdx.x;
    const float2* row = &g_T2[(bf * 31 + shp[0]) * 1984 + shp[1] * 64];
    float ax = 0.0f, ay = 0.0f;
    #pragma unroll 8
    for (int j = 0; j < 64; j++) {
        float2 v = row[j];
        float w = wan[j];
        ax += v.x * w;
        ay += v.y * w;
    }
    g_xc[s * 128 + bf] = make_float2(ax, ay);
}

// ---------------- yc[s][io] = sum_g KT[g][io] * D[s][g] ----------------
// block per s: 5456 blocks x 512 threads
__global__ void k_yc() {
    int s = blockIdx.x;
    __shared__ float2 ds[72];
    int t = threadIdx.x;
    if (t < 72) ds[t] = g_D[s * 72 + t];
    __syncthreads();
    float ax = 0.0f, ay = 0.0f;
    #pragma unroll 8
    for (int g = 0; g < 72; g++) {
        float k = g_KT[g * 512 + t];
        float2 d = ds[g];
        ax += k * d.x;
        ay += k * d.y;
    }
    g_yc[s * 512 + t] = make_float2(ax, ay);
}

// ---------------- main block-diagonal complex GEMM ----------------
// zc[(l,m,n)][b][o] = sum_{k,i} xc[(l,m,k)][b*16+i] * yc[(l,k,n)][i*32+o]
// block per s: 5456 blocks x 256 threads
__global__ void k_ze() {
    int s = blockIdx.x;
    __shared__ float2 xcs[8 * 128];
    __shared__ float2 ycs[8 * 512];
    __shared__ int shp[3];            // d, xbase, ybase
    if (threadIdx.x == 0) {
        int l = 0; while (c_OFF[l+1] <= s) l++;
        int d = 2*l + 1;
        int rem = s - c_OFF[l];
        shp[0] = d;
        shp[1] = c_OFF[l] + (rem / d) * d;   // xbase + k
        shp[2] = c_OFF[l] + (rem % d);       // ybase + k*d
    }
    __syncthreads();
    int d = shp[0], xbase = shp[1], ybase = shp[2];
    int tid = threadIdx.x;
    int b = tid >> 5, o = tid & 31;
    float ax = 0.0f, ay = 0.0f;
    for (int k0 = 0; k0 < d; k0 += 8) {
        int kc = d - k0; if (kc > 8) kc = 8;
        for (int idx = tid; idx < kc * 128; idx += 256) {
            int kk = idx >> 7, t = idx & 127;
            xcs[idx] = g_xc[(xbase + k0 + kk) * 128 + t];
        }
        for (int idx = tid; idx < kc * 512; idx += 256) {
            int kk = idx >> 9, t = idx & 511;
            ycs[idx] = g_yc[(ybase + (k0 + kk) * d) * 512 + t];
        }
        __syncthreads();
        for (int kk = 0; kk < kc; kk++) {
            #pragma unroll
            for (int i = 0; i < 16; i++) {
                float2 a = xcs[kk * 128 + b * 16 + i];
                float2 w = ycs[kk * 512 + i * 32 + o];
                ax += a.x * w.x - a.y * w.y;
                ay += a.x * w.y + a.y * w.x;
            }
        }
        __syncthreads();
    }
    g_zc[s * 256 + tid] = make_float2(ax, ay);
}

// ---------------- l-reduction with Wsy: Zsum[mi][ni][j][bo] ----------------
// block per (mi, ni): 961 blocks x 256 threads
__global__ void k_zsum() {
    int mi = blockIdx.x / 31, ni = blockIdx.x % 31;
    int m = mi - 15, n = ni - 15;
    int am = m < 0 ? -m : m, an = n < 0 ? -n : n;
    int lmin = am > an ? am : an;
    int nl = 16 - lmin;
    __shared__ float ws[16 * 32];
    __shared__ int srow[16];
    int tid = threadIdx.x;
    if (tid < nl) {
        int l = lmin + tid;
        srow[tid] = c_OFF[l] + (m + l) * (2*l + 1) + (n + l);
    }
    __syncthreads();
    for (int idx = tid; idx < nl * 32; idx += 256) {
        int li = idx >> 5, j = idx & 31;
        ws[idx] = g_Wsy[srow[li] * 32 + j];
    }
    __syncthreads();
    float2 acc[32];
    #pragma unroll
    for (int j = 0; j < 32; j++) acc[j] = make_float2(0.0f, 0.0f);
    for (int li = 0; li < nl; li++) {
        float2 z = g_zc[srow[li] * 256 + tid];
        #pragma unroll
        for (int j = 0; j < 32; j++) {
            float w = ws[li * 32 + j];
            acc[j].x += z.x * w;
            acc[j].y += z.y * w;
        }
    }
    int base = (mi * 31 + ni) * 8192 + tid;
    #pragma unroll
    for (int j = 0; j < 32; j++)
        g_Zsum[base + j * 256] = acc[j];
}

// ---------------- inverse DFT over m-axis: U1[a][ni][j][bo] ----------------
// block per (ni, j, half): 1984 blocks x 128 threads
__global__ void k_g1() {
    int bid = blockIdx.x;
    int half = bid & 1;
    int j = (bid >> 1) & 31;
    int ni = bid >> 6;
    __shared__ float2 zin[31 * 128];
    __shared__ float2 twa[992];     // [a=32][mi=31]  e^{+2*pi*i*a*m/32}
    int tid = threadIdx.x;
    for (int idx = tid; idx < 31 * 128; idx += 128) {
        int mi = idx >> 7, t = idx & 127;
        zin[idx] = g_Zsum[(mi * 31 + ni) * 8192 + j * 256 + half * 128 + t];
    }
    for (int idx = tid; idx < 992; idx += 128) {
        int a = idx / 31, mi = idx % 31;
        float ang = 0.1963495408f * (float)(a * (mi - 15));   // pi/16 * a * m
        float sv, cv; sincosf(ang, &sv, &cv);
        twa[idx] = make_float2(cv, sv);
    }
    __syncthreads();
    for (int a = 0; a < 32; a++) {
        float ax = 0.0f, ay = 0.0f;
        #pragma unroll
        for (int mi = 0; mi < 31; mi++) {
            float2 z = zin[mi * 128 + tid];
            float2 t = twa[a * 31 + mi];
            ax += z.x * t.x - z.y * t.y;
            ay += z.x * t.y + z.y * t.x;
        }
        g_U1[((a * 31 + ni) * 32 + j) * 256 + half * 128 + tid] = make_float2(ax, ay);
    }
}

// ---------------- inverse DFT over n-axis, real part, + bias ----------------
// block per (a, j, half): 2048 blocks x 128 threads
__global__ void k_g2(const float* __restrict__ bias, float* __restrict__ out) {
    int bid = blockIdx.x;
    int half = bid & 1;
    int j = (bid >> 1) & 31;
    int a = bid >> 6;
    __shared__ float2 uin[31 * 128];
    __shared__ float2 twc[992];     // [c=32][ni=31]  e^{+2*pi*i*c*n/32}
    int tid = threadIdx.x;
    for (int idx = tid; idx < 31 * 128; idx += 128) {
        int ni = idx >> 7, t = idx & 127;
        uin[idx] = g_U1[((a * 31 + ni) * 32 + j) * 256 + half * 128 + t];
    }
    for (int idx = tid; idx < 992; idx += 128) {
        int c = idx / 31, ni = idx % 31;
        float ang = 0.1963495408f * (float)(c * (ni - 15));
        float sv, cv; sincosf(ang, &sv, &cv);
        twc[idx] = make_float2(cv, sv);
    }
    __syncthreads();
    int bo = half * 128 + tid;
    float bv = bias[bo & 31];
    float v[32];
    #pragma unroll
    for (int c = 0; c < 32; c++) v[c] = bv;
    for (int ni = 0; ni < 31; ni++) {
        float2 u = uin[ni * 128 + tid];
        #pragma unroll
        for (int c = 0; c < 32; c++) {
            float2 t = twc[c * 31 + ni];
            v[c] += u.x * t.x - u.y * t.y;   // Re(u * e^{+i th})
        }
    }
    float4* op = (float4*)(out + (long)bo * 32768 + a * 1024 + j * 32);
    #pragma unroll
    for (int q = 0; q < 8; q++)
        op[q] = make_float4(v[4*q], v[4*q+1], v[4*q+2], v[4*q+3]);
}

// ---------------- launch ----------------
extern "C" void kernel_launch(void* const* d_in, const int* in_sizes, int n_in,
                              void* d_out, int out_size) {
    const float* x    = (const float*)d_in[0];   // [8,16,64,64,64]
    const float* ker  = (const float*)d_in[1];   // [16,32,72]
    const float* bias = (const float*)d_in[2];   // [32]
    const float* ge   = (const float*)d_in[3];   // [72,3]
    float* out = (float*)d_out;                  // [8,32,32,32,32]

    k_init  <<<144, 256>>>(ker);
    k_wigner<<<NSPEC, 192>>>(ge);
    k_dftA  <<<8192, 256>>>(x);
    k_dftC  <<<3968, 256>>>();
    k_xc    <<<NSPEC, 128>>>();
    k_yc    <<<NSPEC, 512>>>();
    k_ze    <<<NSPEC, 256>>>();
    k_zsum  <<<961, 256>>>();
    k_g1    <<<1984, 128>>>();
    k_g2    <<<2048, 128>>>(bias, out);
}

// round 7
// speedup vs baseline: 1.6976x; 1.6976x over previous
#include <cuda_runtime.h>
#include <cuda_bf16.h>
#include <math.h>

// ---------------- constants ----------------
#define NSPEC 5456
#define PI_F 3.14159265358979323846f

__constant__ int c_OFF[17] = {0,1,10,35,84,165,286,455,680,969,1330,1771,2300,2925,3654,4495,5456};

typedef unsigned long long u64;

// ---------------- f32x2 packed helpers ----------------
__device__ __forceinline__ u64 pk(float lo, float hi) {
    u64 r; asm("mov.b64 %0,{%1,%2};" : "=l"(r) : "f"(lo), "f"(hi)); return r;
}
__device__ __forceinline__ u64 fma2(u64 a, u64 b, u64 c) {
    u64 r; asm("fma.rn.f32x2 %0,%1,%2,%3;" : "=l"(r) : "l"(a), "l"(b), "l"(c)); return r;
}
__device__ __forceinline__ void upk(u64 v, float& lo, float& hi) {
    asm("mov.b64 {%0,%1},%2;" : "=f"(lo), "=f"(hi) : "l"(v));
}

// ---------------- scratch (static device globals; no allocation) ----------------
__device__ float2 g_T1[8388608];     // [bf=128][m=16][j=64][c=64]   (m >= 0 only)
__device__ float2 g_T2[7872512];     // [bf=128][mi=31][ni=31][j=64]
__device__ float  g_Wan[NSPEC*64];
__device__ float  g_Wsy[NSPEC*32];
__device__ float2 g_D[NSPEC*72];
__device__ float  g_wquad[64];
__device__ float  g_KT[72*512];
__device__ float2 g_xc[NSPEC*128];   // [s][b*16+f]
__device__ float2 g_yc[NSPEC*512];   // [s][i*32+o]
__device__ float2 g_zc[NSPEC*256];   // [s][b*32+o]
__device__ float2 g_Zsum[7872512];   // [mi=31][ni=31][j=32][bo=256]
__device__ float2 g_U1[8126464];     // [a=32][ni=31][j=32][bo=256]

// ---------------- init ----------------
__global__ void k_init(const float* __restrict__ ker) {
    int idx = blockIdx.x * blockDim.x + threadIdx.x;
    if (idx < 36864) {
        int g  = idx >> 9;
        int io = idx & 511;
        g_KT[idx] = ker[io * 72 + g] * (1.0f / 12.0f);
    }
    if (idx < 64) {
        int j = idx;
        float inner = 0.0f;
        for (int k = 0; k < 32; k++)
            inner += sinf((float)((2*j+1)*(2*k+1)) * PI_F / 128.0f) / (float)(2*k+1);
        float w = (2.0f / 32.0f) * sinf(PI_F * (float)(2*j+1) / 128.0f) * inner;
        g_wquad[j] = w / 4096.0f;
    }
}

// ---------------- Wigner tables ----------------
__global__ void k_wigner(const float* __restrict__ ge) {
    int s = blockIdx.x;
    __shared__ float lcoef[32];
    __shared__ int shp[5];
    if (threadIdx.x == 0) {
        int l = 0; while (c_OFF[l+1] <= s) l++;
        int dsz = 2*l + 1;
        int rem = s - c_OFF[l];
        int M = rem / dsz - l;
        int N = rem % dsz - l;
        int Kmin = (M - N) > 0 ? (M - N) : 0;
        int Kmax = (l + M) < (l - N) ? (l + M) : (l - N);
        double lf[32];
        lf[0] = 0.0;
        for (int i = 1; i < 32; i++) lf[i] = lf[i-1] + log((double)i);
        double lgA = 0.5 * (lf[l+M] + lf[l-M] + lf[l+N] + lf[l-N]);
        for (int K = Kmin; K <= Kmax; K++)
            lcoef[K] = (float)(lgA - (lf[K] + lf[l+M-K] + lf[l-N-K] + lf[N-M+K]));
        shp[0] = l; shp[1] = M; shp[2] = N; shp[3] = Kmin; shp[4] = Kmax;
    }
    __syncthreads();
    int t = threadIdx.x;
    if (t >= 168) return;
    int l = shp[0], M = shp[1], N = shp[2], Kmin = shp[3], Kmax = shp[4];
    float beta;
    if (t < 64)       beta = PI_F * (float)(2*t + 1) / 128.0f;
    else if (t < 96)  beta = PI_F * (float)(2*(t-64) + 1) / 64.0f;
    else              beta = ge[(t - 96) * 3 + 1];
    float ch  = cosf(0.5f * beta);
    float shv = sinf(0.5f * beta);
    float lc  = logf(ch);
    float lsn = logf(shv);
    float dval = 0.0f;
    for (int K = Kmin; K <= Kmax; K++) {
        int e1 = 2*l + M - N - 2*K;
        int e2 = N - M + 2*K;
        float arg = lcoef[K];
        if (e1) arg += (float)e1 * lc;
        if (e2) arg += (float)e2 * lsn;
        float term = expf(arg);
        dval += (K & 1) ? -term : term;
    }
    if (t < 64) {
        g_Wan[s * 64 + t] = dval * g_wquad[t];
    } else if (t < 96) {
        g_Wsy[s * 32 + (t - 64)] = dval * (float)(2*l + 1);
    } else {
        int g = t - 96;
        float alpha = ge[g*3 + 0], gamma = ge[g*3 + 2];
        float th = (float)M * alpha + (float)N * gamma;
        float sv, cv; sincosf(th, &sv, &cv);
        g_D[s * 72 + g] = make_float2(dval * cv, -dval * sv);
    }
}

// ---------------- Stage A: DFT over first spatial axis (real input, m=0..15) ----------------
// block per (bf, j): 8192 blocks x 256 threads
__global__ void k_dftA(const float* __restrict__ x) {
    __shared__ float sx[64 * 66];     // [c][a] padded
    __shared__ float twC[16 * 64];    // [m][a] cos
    __shared__ float twS[16 * 64];    // [m][a] sin
    int bid = blockIdx.x;
    int j = bid & 63, bf = bid >> 6;
    int tid = threadIdx.x;
    for (int idx = tid; idx < 4096; idx += 256) {
        int a = idx >> 6, c = idx & 63;
        sx[c * 66 + a] = x[bf * 262144 + a * 4096 + j * 64 + c];
    }
    for (int idx = tid; idx < 1024; idx += 256) {
        int m = idx >> 6, a = idx & 63;
        float sv, cv; sincosf(0.0981747704f * (float)(a * m), &sv, &cv);  // pi/32 * a*m
        twC[idx] = cv; twS[idx] = sv;
    }
    __syncthreads();
    int c = tid & 63, m0 = tid >> 6;       // m = m0*4 + it
    u64 aC[4], aS[4];
    #pragma unroll
    for (int it = 0; it < 4; it++) { aC[it] = 0ULL; aS[it] = 0ULL; }
    for (int a = 0; a < 64; a += 2) {
        u64 xv = *(const u64*)&sx[c * 66 + a];
        #pragma unroll
        for (int it = 0; it < 4; it++) {
            int m = m0 * 4 + it;
            u64 tc = *(const u64*)&twC[m * 64 + a];
            u64 ts = *(const u64*)&twS[m * 64 + a];
            aC[it] = fma2(xv, tc, aC[it]);
            aS[it] = fma2(xv, ts, aS[it]);
        }
    }
    #pragma unroll
    for (int it = 0; it < 4; it++) {
        int m = m0 * 4 + it;
        float c1, c2, s1, s2;
        upk(aC[it], c1, c2); upk(aS[it], s1, s2);
        // twiddle e^{-i th}: real = sum x cos, imag = -sum x sin
        g_T1[bf * 65536 + m * 4096 + j * 64 + c] = make_float2(c1 + c2, -(s1 + s2));
    }
}

// ---------------- Stage C: DFT over third spatial axis (pair symmetry over n) ----------------
// block per (bf, mi): 3968 blocks x 256 threads
__global__ void k_dftC() {
    __shared__ float sTx[64 * 66];    // [j][c] padded
    __shared__ float sTy[64 * 66];
    __shared__ float twQC[16 * 64];   // [q][c] cos(q c pi/32)
    __shared__ float twQS[16 * 64];
    int bid = blockIdx.x;
    int bf = bid / 31, mi = bid % 31;
    int m = mi - 15;
    int am = m < 0 ? -m : m;
    float sgn = (m < 0) ? -1.0f : 1.0f;
    int tid = threadIdx.x;
    const float2* src = &g_T1[bf * 65536 + am * 4096];
    for (int idx = tid; idx < 4096; idx += 256) {
        float2 v = src[idx];
        int jj = idx >> 6, c = idx & 63;
        sTx[jj * 66 + c] = v.x;
        sTy[jj * 66 + c] = sgn * v.y;
    }
    for (int idx = tid; idx < 1024; idx += 256) {
        int q = idx >> 6, c = idx & 63;
        float sv, cv; sincosf(0.0981747704f * (float)(q * c), &sv, &cv);
        twQC[idx] = cv; twQS[idx] = sv;
    }
    __syncthreads();
    int j = tid & 63, q0 = tid >> 6;
    float2* dst = &g_T2[(bf * 31 + mi) * 1984];
    u64 A[16];   // per it: Axc, AxS, Ayc, AyS
    #pragma unroll
    for (int i = 0; i < 16; i++) A[i] = 0ULL;
    for (int c = 0; c < 64; c += 2) {
        u64 axv = *(const u64*)&sTx[j * 66 + c];
        u64 ayv = *(const u64*)&sTy[j * 66 + c];
        #pragma unroll
        for (int it = 0; it < 4; it++) {
            int q = q0 + 4 * it;
            u64 tc = *(const u64*)&twQC[q * 64 + c];
            u64 ts = *(const u64*)&twQS[q * 64 + c];
            A[it*4+0] = fma2(axv, tc, A[it*4+0]);
            A[it*4+1] = fma2(axv, ts, A[it*4+1]);
            A[it*4+2] = fma2(ayv, tc, A[it*4+2]);
            A[it*4+3] = fma2(ayv, ts, A[it*4+3]);
        }
    }
    #pragma unroll
    for (int it = 0; it < 4; it++) {
        int q = q0 + 4 * it;
        float a1, a2;
        float Sxc, SxS, Syc, SyS;
        upk(A[it*4+0], a1, a2); Sxc = a1 + a2;
        upk(A[it*4+1], a1, a2); SxS = a1 + a2;
        upk(A[it*4+2], a1, a2); Syc = a1 + a2;
        upk(A[it*4+3], a1, a2); SyS = a1 + a2;
        // n=+q (ni=15+q):  t=(cos,-sin) -> (Sxc+SyS, Syc-SxS)
        dst[(15 + q) * 64 + j] = make_float2(Sxc + SyS, Syc - SxS);
        if (q > 0)
            dst[(15 - q) * 64 + j] = make_float2(Sxc - SyS, Syc + SxS);
    }
}

// ---------------- xc ----------------
__global__ void k_xc() {
    int s = blockIdx.x;
    __shared__ float wan[64];
    __shared__ int shp[2];
    if (threadIdx.x == 0) {
        int l = 0; while (c_OFF[l+1] <= s) l++;
        int dsz = 2*l + 1;
        int rem = s - c_OFF[l];
        shp[0] = rem / dsz - l + 15;
        shp[1] = rem % dsz - l + 15;
    }
    if (threadIdx.x < 64) wan[threadIdx.x] = g_Wan[s * 64 + threadIdx.x];
    __syncthreads();
    int bf = threadIdx.x;
    const float2* row = &g_T2[(bf * 31 + shp[0]) * 1984 + shp[1] * 64];
    float ax = 0.0f, ay = 0.0f;
    #pragma unroll 8
    for (int j = 0; j < 64; j++) {
        float2 v = row[j];
        float w = wan[j];
        ax += v.x * w;
        ay += v.y * w;
    }
    g_xc[s * 128 + bf] = make_float2(ax, ay);
}

// ---------------- yc ----------------
__global__ void k_yc() {
    int s = blockIdx.x;
    __shared__ float2 ds[72];
    int t = threadIdx.x;
    if (t < 72) ds[t] = g_D[s * 72 + t];
    __syncthreads();
    float ax = 0.0f, ay = 0.0f;
    #pragma unroll 8
    for (int g = 0; g < 72; g++) {
        float k = g_KT[g * 512 + t];
        float2 d = ds[g];
        ax += k * d.x;
        ay += k * d.y;
    }
    g_yc[s * 512 + t] = make_float2(ax, ay);
}

// ---------------- main block-diagonal complex GEMM (warp-split-k, f32x2) ----------------
// block per s: 5456 blocks x 128 threads. Warp w handles k = k0 + w within each 4-chunk.
// Each thread owns lane=o column with 8 packed (zx,zy) accumulators over b.
__global__ void k_ze() {
    int s = blockIdx.x;
    __shared__ u64   xp1[4 * 128];     // [k][i*8+b] = (a.x, a.x)
    __shared__ u64   xp2[4 * 128];     // [k][i*8+b] = (-a.y, a.y)
    __shared__ float2 ycs[4 * 512];    // [k][i*32+o]
    __shared__ u64   red[4 * 32 * 8];  // cross-warp reduction
    __shared__ int shp[3];
    int tid = threadIdx.x;
    int w = tid >> 5, lane = tid & 31;
    if (tid == 0) {
        int l = 0; while (c_OFF[l+1] <= s) l++;
        int d = 2*l + 1;
        int rem = s - c_OFF[l];
        shp[0] = d;
        shp[1] = c_OFF[l] + (rem / d) * d;
        shp[2] = c_OFF[l] + (rem % d);
    }
    __syncthreads();
    int d = shp[0], xbase = shp[1], ybase = shp[2];
    u64 acc[8];
    #pragma unroll
    for (int b = 0; b < 8; b++) acc[b] = 0ULL;
    for (int k0 = 0; k0 < d; k0 += 4) {
        int kc = d - k0; if (kc > 4) kc = 4;
        __syncthreads();
        for (int idx = tid; idx < kc * 128; idx += 128) {
            int kk = idx >> 7, r = idx & 127;
            int i = r & 15, b = r >> 4;
            float2 v = g_xc[(xbase + k0 + kk) * 128 + r];
            xp1[kk * 128 + i * 8 + b] = pk(v.x, v.x);
            xp2[kk * 128 + i * 8 + b] = pk(-v.y, v.y);
        }
        for (int idx = tid; idx < kc * 512; idx += 128) {
            int kk = idx >> 9, t = idx & 511;
            ycs[idx] = g_yc[(ybase + (k0 + kk) * d) * 512 + t];
        }
        __syncthreads();
        if (w < kc) {
            #pragma unroll
            for (int i = 0; i < 16; i++) {
                float2 wv2 = ycs[w * 512 + i * 32 + lane];
                u64 wv  = pk(wv2.x, wv2.y);
                u64 wsw = pk(wv2.y, wv2.x);
                #pragma unroll
                for (int b2 = 0; b2 < 4; b2++) {
                    ulonglong2 x1 = *(const ulonglong2*)&xp1[w * 128 + i * 8 + b2 * 2];
                    ulonglong2 x2 = *(const ulonglong2*)&xp2[w * 128 + i * 8 + b2 * 2];
                    acc[b2*2]   = fma2(x1.x, wv,  acc[b2*2]);
                    acc[b2*2]   = fma2(x2.x, wsw, acc[b2*2]);
                    acc[b2*2+1] = fma2(x1.y, wv,  acc[b2*2+1]);
                    acc[b2*2+1] = fma2(x2.y, wsw, acc[b2*2+1]);
                }
            }
        }
    }
    __syncthreads();
    #pragma unroll
    for (int b = 0; b < 8; b++) red[(w * 32 + lane) * 8 + b] = acc[b];
    __syncthreads();
    for (int t = tid; t < 256; t += 128) {
        int o = t & 31, b = t >> 5;
        float sx = 0.0f, sy = 0.0f;
        #pragma unroll
        for (int ww = 0; ww < 4; ww++) {
            float lo, hi; upk(red[(ww * 32 + o) * 8 + b], lo, hi);
            sx += lo; sy += hi;
        }
        g_zc[s * 256 + b * 32 + o] = make_float2(sx, sy);
    }
}

// ---------------- l-reduction with Wsy ----------------
__global__ void k_zsum() {
    int mi = blockIdx.x / 31, ni = blockIdx.x % 31;
    int m = mi - 15, n = ni - 15;
    int am = m < 0 ? -m : m, an = n < 0 ? -n : n;
    int lmin = am > an ? am : an;
    int nl = 16 - lmin;
    __shared__ float ws[16 * 32];
    __shared__ int srow[16];
    int tid = threadIdx.x;
    if (tid < nl) {
        int l = lmin + tid;
        srow[tid] = c_OFF[l] + (m + l) * (2*l + 1) + (n + l);
    }
    __syncthreads();
    for (int idx = tid; idx < nl * 32; idx += 256) {
        int li = idx >> 5, j = idx & 31;
        ws[idx] = g_Wsy[srow[li] * 32 + j];
    }
    __syncthreads();
    float2 acc[32];
    #pragma unroll
    for (int j = 0; j < 32; j++) acc[j] = make_float2(0.0f, 0.0f);
    for (int li = 0; li < nl; li++) {
        float2 z = g_zc[srow[li] * 256 + tid];
        #pragma unroll
        for (int j = 0; j < 32; j++) {
            float w = ws[li * 32 + j];
            acc[j].x += z.x * w;
            acc[j].y += z.y * w;
        }
    }
    int base = (mi * 31 + ni) * 8192 + tid;
    #pragma unroll
    for (int j = 0; j < 32; j++)
        g_Zsum[base + j * 256] = acc[j];
}

// ---------------- inverse DFT over m-axis (mi outer, 32 packed accumulators) ----------------
// block per (ni, j, half): 1984 blocks x 128 threads
__global__ void k_g1() {
    int bid = blockIdx.x;
    int half = bid & 1;
    int j = (bid >> 1) & 31;
    int ni = bid >> 6;
    __shared__ float2 zin[31 * 128];
    __shared__ float2 twa[992];     // [a*31+mi] = (cos, sin) of +a*m*pi/16
    int tid = threadIdx.x;
    for (int idx = tid; idx < 31 * 128; idx += 128)
        zin[idx] = g_Zsum[((idx >> 7) * 31 + ni) * 8192 + j * 256 + half * 128 + (idx & 127)];
    for (int idx = tid; idx < 992; idx += 128) {
        int a = idx / 31, mi = idx % 31;
        float sv, cv; sincosf(0.1963495408f * (float)(a * (mi - 15)), &sv, &cv);
        twa[idx] = make_float2(cv, sv);
    }
    __syncthreads();
    u64 acc[32];
    #pragma unroll
    for (int a = 0; a < 32; a++) acc[a] = 0ULL;
    for (int mi = 0; mi < 31; mi++) {
        float2 z = zin[mi * 128 + tid];
        u64 zx = pk(z.x, z.x);
        u64 zy = pk(-z.y, z.y);
        #pragma unroll
        for (int a = 0; a < 32; a++) {
            float2 t = twa[a * 31 + mi];
            acc[a] = fma2(zx, pk(t.x, t.y), acc[a]);
            acc[a] = fma2(zy, pk(t.y, t.x), acc[a]);
        }
    }
    #pragma unroll
    for (int a = 0; a < 32; a++) {
        float lo, hi; upk(acc[a], lo, hi);
        g_U1[((a * 31 + ni) * 32 + j) * 256 + half * 128 + tid] = make_float2(lo, hi);
    }
}

// ---------------- inverse DFT over n-axis, real part, + bias (ni outer) ----------------
// block per (a, j, half): 2048 blocks x 128 threads
__global__ void k_g2(const float* __restrict__ bias, float* __restrict__ out) {
    int bid = blockIdx.x;
    int half = bid & 1;
    int j = (bid >> 1) & 31;
    int a = bid >> 6;
    __shared__ float2 uin[31 * 128];
    __shared__ float twcC[992];    // [ni*32+c]
    __shared__ float twcS[992];
    int tid = threadIdx.x;
    for (int idx = tid; idx < 31 * 128; idx += 128)
        uin[idx] = g_U1[((a * 31 + (idx >> 7)) * 32 + j) * 256 + half * 128 + (idx & 127)];
    for (int idx = tid; idx < 992; idx += 128) {
        int ni = idx >> 5, c = idx & 31;
        float sv, cv; sincosf(0.1963495408f * (float)(c * (ni - 15)), &sv, &cv);
        twcC[idx] = cv; twcS[idx] = sv;
    }
    __syncthreads();
    int bo = half * 128 + tid;
    float bv = bias[bo & 31];
    u64 v2[16];
    #pragma unroll
    for (int q = 0; q < 16; q++) v2[q] = pk(bv, bv);
    for (int ni = 0; ni < 31; ni++) {
        float2 u = uin[ni * 128 + tid];
        u64 ux  = pk(u.x, u.x);
        u64 nuy = pk(-u.y, -u.y);
        #pragma unroll
        for (int q = 0; q < 16; q++) {
            u64 tc = *(const u64*)&twcC[ni * 32 + q * 2];
            u64 ts = *(const u64*)&twcS[ni * 32 + q * 2];
            v2[q] = fma2(ux, tc, v2[q]);
            v2[q] = fma2(nuy, ts, v2[q]);
        }
    }
    float v[32];
    #pragma unroll
    for (int q = 0; q < 16; q++) upk(v2[q], v[2*q], v[2*q+1]);
    float4* op = (float4*)(out + (long)bo * 32768 + a * 1024 + j * 32);
    #pragma unroll
    for (int q2 = 0; q2 < 8; q2++)
        op[q2] = make_float4(v[4*q2], v[4*q2+1], v[4*q2+2], v[4*q2+3]);
}

// ---------------- launch ----------------
extern "C" void kernel_launch(void* const* d_in, const int* in_sizes, int n_in,
                              void* d_out, int out_size) {
    const float* x    = (const float*)d_in[0];   // [8,16,64,64,64]
    const float* ker  = (const float*)d_in[1];   // [16,32,72]
    const float* bias = (const float*)d_in[2];   // [32]
    const float* ge   = (const float*)d_in[3];   // [72,3]
    float* out = (float*)d_out;                  // [8,32,32,32,32]

    k_init  <<<144, 256>>>(ker);
    k_wigner<<<NSPEC, 192>>>(ge);
    k_dftA  <<<8192, 256>>>(x);
    k_dftC  <<<3968, 256>>>();
    k_xc    <<<NSPEC, 128>>>();
    k_yc    <<<NSPEC, 512>>>();
    k_ze    <<<NSPEC, 128>>>();
    k_zsum  <<<961, 256>>>();
    k_g1    <<<1984, 128>>>();
    k_g2    <<<2048, 128>>>(bias, out);
}

// round 8
// speedup vs baseline: 1.9315x; 1.1377x over previous
#include <cuda_runtime.h>
#include <cuda_bf16.h>
#include <math.h>

// ---------------- constants ----------------
#define NSPEC 5456
#define PI_F 3.14159265358979323846f

__constant__ int c_OFF[17] = {0,1,10,35,84,165,286,455,680,969,1330,1771,2300,2925,3654,4495,5456};

typedef unsigned long long u64;

// ---------------- f32x2 packed helpers ----------------
__device__ __forceinline__ u64 pk(float lo, float hi) {
    u64 r; asm("mov.b64 %0,{%1,%2};" : "=l"(r) : "f"(lo), "f"(hi)); return r;
}
__device__ __forceinline__ u64 fma2(u64 a, u64 b, u64 c) {
    u64 r; asm("fma.rn.f32x2 %0,%1,%2,%3;" : "=l"(r) : "l"(a), "l"(b), "l"(c)); return r;
}
__device__ __forceinline__ u64 add2(u64 a, u64 b) {
    u64 r; asm("add.rn.f32x2 %0,%1,%2;" : "=l"(r) : "l"(a), "l"(b)); return r;
}
__device__ __forceinline__ void upk(u64 v, float& lo, float& hi) {
    asm("mov.b64 {%0,%1},%2;" : "=f"(lo), "=f"(hi) : "l"(v));
}

// ---------------- scratch (static device globals; no allocation) ----------------
__device__ float2 g_T1[8388608];     // [bf=128][m=16][j=64][c=64]   (m >= 0 only)
__device__ float2 g_T2[7872512];     // [bf=128][mi=31][ni=31][j=64]
__device__ float  g_Wan[NSPEC*64];
__device__ float  g_Wsy[NSPEC*32];
__device__ float2 g_D[NSPEC*72];
__device__ float  g_wquad[64];
__device__ float  g_KT[72*512];
__device__ float2 g_xc[NSPEC*128];   // [s][b*16+f]
__device__ float2 g_yc[NSPEC*512];   // [s][i*32+o]
__device__ float2 g_zc[NSPEC*256];   // [s][b*32+o]
__device__ float2 g_Zsum[7872512];   // [mi=31][ni=31][j=32][bo=256]
__device__ float2 g_U1[8126464];     // [a=32][ni=31][j=32][bo=256]

// ---------------- init ----------------
__global__ void k_init(const float* __restrict__ ker) {
    int idx = blockIdx.x * blockDim.x + threadIdx.x;
    if (idx < 36864) {
        int g  = idx >> 9;
        int io = idx & 511;
        g_KT[idx] = ker[io * 72 + g] * (1.0f / 12.0f);
    }
    if (idx < 64) {
        int j = idx;
        float inner = 0.0f;
        for (int k = 0; k < 32; k++)
            inner += sinf((float)((2*j+1)*(2*k+1)) * PI_F / 128.0f) / (float)(2*k+1);
        float w = (2.0f / 32.0f) * sinf(PI_F * (float)(2*j+1) / 128.0f) * inner;
        g_wquad[j] = w / 4096.0f;
    }
}

// ---------------- Wigner tables ----------------
__global__ void k_wigner(const float* __restrict__ ge) {
    int s = blockIdx.x;
    __shared__ float lcoef[32];
    __shared__ int shp[5];
    if (threadIdx.x == 0) {
        int l = 0; while (c_OFF[l+1] <= s) l++;
        int dsz = 2*l + 1;
        int rem = s - c_OFF[l];
        int M = rem / dsz - l;
        int N = rem % dsz - l;
        int Kmin = (M - N) > 0 ? (M - N) : 0;
        int Kmax = (l + M) < (l - N) ? (l + M) : (l - N);
        double lf[32];
        lf[0] = 0.0;
        for (int i = 1; i < 32; i++) lf[i] = lf[i-1] + log((double)i);
        double lgA = 0.5 * (lf[l+M] + lf[l-M] + lf[l+N] + lf[l-N]);
        for (int K = Kmin; K <= Kmax; K++)
            lcoef[K] = (float)(lgA - (lf[K] + lf[l+M-K] + lf[l-N-K] + lf[N-M+K]));
        shp[0] = l; shp[1] = M; shp[2] = N; shp[3] = Kmin; shp[4] = Kmax;
    }
    __syncthreads();
    int t = threadIdx.x;
    if (t >= 168) return;
    int l = shp[0], M = shp[1], N = shp[2], Kmin = shp[3], Kmax = shp[4];
    float beta;
    if (t < 64)       beta = PI_F * (float)(2*t + 1) / 128.0f;
    else if (t < 96)  beta = PI_F * (float)(2*(t-64) + 1) / 64.0f;
    else              beta = ge[(t - 96) * 3 + 1];
    float ch  = cosf(0.5f * beta);
    float shv = sinf(0.5f * beta);
    float lc  = logf(ch);
    float lsn = logf(shv);
    float dval = 0.0f;
    for (int K = Kmin; K <= Kmax; K++) {
        int e1 = 2*l + M - N - 2*K;
        int e2 = N - M + 2*K;
        float arg = lcoef[K];
        if (e1) arg += (float)e1 * lc;
        if (e2) arg += (float)e2 * lsn;
        float term = expf(arg);
        dval += (K & 1) ? -term : term;
    }
    if (t < 64) {
        g_Wan[s * 64 + t] = dval * g_wquad[t];
    } else if (t < 96) {
        g_Wsy[s * 32 + (t - 64)] = dval * (float)(2*l + 1);
    } else {
        int g = t - 96;
        float alpha = ge[g*3 + 0], gamma = ge[g*3 + 2];
        float th = (float)M * alpha + (float)N * gamma;
        float sv, cv; sincosf(th, &sv, &cv);
        g_D[s * 72 + g] = make_float2(dval * cv, -dval * sv);
    }
}

// ---------------- Stage A: DFT over first axis, a-folded (x[a] +/- x[a+32]) ----------------
// block per (bf, j): 8192 blocks x 256 threads = (c 0..63) x (m0 0..3)
__global__ void k_dftA(const float* __restrict__ x) {
    __shared__ __align__(16) float sxu[64 * 36];   // [c][a0..31] padded 36
    __shared__ __align__(16) float sxv[64 * 36];
    __shared__ __align__(16) float twC[16 * 32];   // [m][a0..31]
    __shared__ __align__(16) float twS[16 * 32];
    int bid = blockIdx.x;
    int j = bid & 63, bf = bid >> 6;
    int tid = threadIdx.x;
    const float* xb = x + bf * 262144 + j * 64;
    for (int idx = tid; idx < 2048; idx += 256) {
        int a = idx >> 6, c = idx & 63;
        float xa = xb[a * 4096 + c];
        float xc2 = xb[(a + 32) * 4096 + c];
        sxu[c * 36 + a] = xa + xc2;
        sxv[c * 36 + a] = xa - xc2;
    }
    for (int idx = tid; idx < 512; idx += 256) {
        int m = idx >> 5, a = idx & 31;
        float sv, cv; sincosf(0.0981747704f * (float)(a * m), &sv, &cv);  // pi/32 * a*m
        twC[idx] = cv; twS[idx] = sv;
    }
    __syncthreads();
    int c = tid & 63, m0 = tid >> 6;
    u64 aC[4] = {0ULL,0ULL,0ULL,0ULL}, aS[4] = {0ULL,0ULL,0ULL,0ULL};
    for (int a0 = 0; a0 < 32; a0 += 4) {
        ulonglong2 U = *(const ulonglong2*)&sxu[c * 36 + a0];
        ulonglong2 V = *(const ulonglong2*)&sxv[c * 36 + a0];
        #pragma unroll
        for (int it = 0; it < 4; it++) {
            int m = m0 * 4 + it;
            ulonglong2 TC = *(const ulonglong2*)&twC[m * 32 + a0];
            ulonglong2 TS = *(const ulonglong2*)&twS[m * 32 + a0];
            u64 xlo = (it & 1) ? V.x : U.x;     // parity(m) == parity(it)
            u64 xhi = (it & 1) ? V.y : U.y;
            aC[it] = fma2(xlo, TC.x, aC[it]);
            aC[it] = fma2(xhi, TC.y, aC[it]);
            aS[it] = fma2(xlo, TS.x, aS[it]);
            aS[it] = fma2(xhi, TS.y, aS[it]);
        }
    }
    #pragma unroll
    for (int it = 0; it < 4; it++) {
        int m = m0 * 4 + it;
        float c1, c2, s1, s2;
        upk(aC[it], c1, c2); upk(aS[it], s1, s2);
        g_T1[bf * 65536 + m * 4096 + j * 64 + c] = make_float2(c1 + c2, -(s1 + s2));
    }
}

// ---------------- Stage C: DFT over third axis, c-folded + n-sign symmetry ----------------
// block per (bf, mi): 3968 blocks x 256 threads = (j 0..63) x (q0 0..3); q = q0 + 4*it
__global__ void k_dftC() {
    __shared__ __align__(16) float suX[64 * 36];
    __shared__ __align__(16) float suY[64 * 36];
    __shared__ __align__(16) float svX[64 * 36];
    __shared__ __align__(16) float svY[64 * 36];
    __shared__ __align__(16) float twQC[16 * 32];
    __shared__ __align__(16) float twQS[16 * 32];
    int bid = blockIdx.x;
    int bf = bid / 31, mi = bid % 31;
    int m = mi - 15;
    int am = m < 0 ? -m : m;
    float sgn = (m < 0) ? -1.0f : 1.0f;
    int tid = threadIdx.x;
    const float2* src = &g_T1[bf * 65536 + am * 4096];
    for (int idx = tid; idx < 2048; idx += 256) {
        int jj = idx >> 5, c = idx & 31;
        float2 a = src[jj * 64 + c];
        float2 b = src[jj * 64 + c + 32];
        suX[jj * 36 + c] = a.x + b.x;
        svX[jj * 36 + c] = a.x - b.x;
        suY[jj * 36 + c] = sgn * (a.y + b.y);
        svY[jj * 36 + c] = sgn * (a.y - b.y);
    }
    for (int idx = tid; idx < 512; idx += 256) {
        int q = idx >> 5, c = idx & 31;
        float sv, cv; sincosf(0.0981747704f * (float)(q * c), &sv, &cv);
        twQC[idx] = cv; twQS[idx] = sv;
    }
    __syncthreads();
    int j = tid & 63, q0 = tid >> 6;
    const float* sX = (q0 & 1) ? svX : suX;     // parity(q) == parity(q0)
    const float* sY = (q0 & 1) ? svY : suY;
    u64 A[16];
    #pragma unroll
    for (int i = 0; i < 16; i++) A[i] = 0ULL;
    for (int c0 = 0; c0 < 32; c0 += 4) {
        ulonglong2 X = *(const ulonglong2*)&sX[j * 36 + c0];
        ulonglong2 Y = *(const ulonglong2*)&sY[j * 36 + c0];
        #pragma unroll
        for (int it = 0; it < 4; it++) {
            int q = q0 + 4 * it;
            ulonglong2 TC = *(const ulonglong2*)&twQC[q * 32 + c0];
            ulonglong2 TS = *(const ulonglong2*)&twQS[q * 32 + c0];
            A[it*4+0] = fma2(X.x, TC.x, A[it*4+0]);
            A[it*4+0] = fma2(X.y, TC.y, A[it*4+0]);
            A[it*4+1] = fma2(X.x, TS.x, A[it*4+1]);
            A[it*4+1] = fma2(X.y, TS.y, A[it*4+1]);
            A[it*4+2] = fma2(Y.x, TC.x, A[it*4+2]);
            A[it*4+2] = fma2(Y.y, TC.y, A[it*4+2]);
            A[it*4+3] = fma2(Y.x, TS.x, A[it*4+3]);
            A[it*4+3] = fma2(Y.y, TS.y, A[it*4+3]);
        }
    }
    float2* dst = &g_T2[(bf * 31 + mi) * 1984];
    #pragma unroll
    for (int it = 0; it < 4; it++) {
        int q = q0 + 4 * it;
        float a1, a2;
        float Sxc, SxS, Syc, SyS;
        upk(A[it*4+0], a1, a2); Sxc = a1 + a2;
        upk(A[it*4+1], a1, a2); SxS = a1 + a2;
        upk(A[it*4+2], a1, a2); Syc = a1 + a2;
        upk(A[it*4+3], a1, a2); SyS = a1 + a2;
        dst[(15 + q) * 64 + j] = make_float2(Sxc + SyS, Syc - SxS);
        if (q > 0)
            dst[(15 - q) * 64 + j] = make_float2(Sxc - SyS, Syc + SxS);
    }
}

// ---------------- xc ----------------
__global__ void k_xc() {
    int s = blockIdx.x;
    __shared__ float wan[64];
    __shared__ int shp[2];
    if (threadIdx.x == 0) {
        int l = 0; while (c_OFF[l+1] <= s) l++;
        int dsz = 2*l + 1;
        int rem = s - c_OFF[l];
        shp[0] = rem / dsz - l + 15;
        shp[1] = rem % dsz - l + 15;
    }
    if (threadIdx.x < 64) wan[threadIdx.x] = g_Wan[s * 64 + threadIdx.x];
    __syncthreads();
    int bf = threadIdx.x;
    const float2* row = &g_T2[(bf * 31 + shp[0]) * 1984 + shp[1] * 64];
    float ax = 0.0f, ay = 0.0f;
    #pragma unroll 8
    for (int j = 0; j < 64; j++) {
        float2 v = row[j];
        float w = wan[j];
        ax += v.x * w;
        ay += v.y * w;
    }
    g_xc[s * 128 + bf] = make_float2(ax, ay);
}

// ---------------- yc: 4 spectral rows per block ----------------
// grid 1364 blocks x 512 threads
__global__ void k_yc() {
    int s4 = blockIdx.x * 4;
    __shared__ __align__(16) float2 ds[4 * 72];
    int t = threadIdx.x;
    if (t < 288) ds[t] = g_D[s4 * 72 + t];
    __syncthreads();
    u64 a0 = 0ULL, a1 = 0ULL, a2 = 0ULL, a3 = 0ULL;
    #pragma unroll 4
    for (int g = 0; g < 72; g++) {
        float k = g_KT[g * 512 + t];
        u64 k2 = pk(k, k);
        a0 = fma2(k2, *(const u64*)&ds[g],       a0);
        a1 = fma2(k2, *(const u64*)&ds[72 + g],  a1);
        a2 = fma2(k2, *(const u64*)&ds[144 + g], a2);
        a3 = fma2(k2, *(const u64*)&ds[216 + g], a3);
    }
    float lo, hi;
    upk(a0, lo, hi); g_yc[(s4 + 0) * 512 + t] = make_float2(lo, hi);
    upk(a1, lo, hi); g_yc[(s4 + 1) * 512 + t] = make_float2(lo, hi);
    upk(a2, lo, hi); g_yc[(s4 + 2) * 512 + t] = make_float2(lo, hi);
    upk(a3, lo, hi); g_yc[(s4 + 3) * 512 + t] = make_float2(lo, hi);
}

// ---------------- main block-diagonal complex GEMM (unchanged from R6) ----------------
__global__ void k_ze() {
    int s = blockIdx.x;
    __shared__ u64   xp1[4 * 128];
    __shared__ u64   xp2[4 * 128];
    __shared__ float2 ycs[4 * 512];
    __shared__ u64   red[4 * 32 * 8];
    __shared__ int shp[3];
    int tid = threadIdx.x;
    int w = tid >> 5, lane = tid & 31;
    if (tid == 0) {
        int l = 0; while (c_OFF[l+1] <= s) l++;
        int d = 2*l + 1;
        int rem = s - c_OFF[l];
        shp[0] = d;
        shp[1] = c_OFF[l] + (rem / d) * d;
        shp[2] = c_OFF[l] + (rem % d);
    }
    __syncthreads();
    int d = shp[0], xbase = shp[1], ybase = shp[2];
    u64 acc[8];
    #pragma unroll
    for (int b = 0; b < 8; b++) acc[b] = 0ULL;
    for (int k0 = 0; k0 < d; k0 += 4) {
        int kc = d - k0; if (kc > 4) kc = 4;
        __syncthreads();
        for (int idx = tid; idx < kc * 128; idx += 128) {
            int kk = idx >> 7, r = idx & 127;
            int i = r & 15, b = r >> 4;
            float2 v = g_xc[(xbase + k0 + kk) * 128 + r];
            xp1[kk * 128 + i * 8 + b] = pk(v.x, v.x);
            xp2[kk * 128 + i * 8 + b] = pk(-v.y, v.y);
        }
        for (int idx = tid; idx < kc * 512; idx += 128) {
            int kk = idx >> 9, t = idx & 511;
            ycs[idx] = g_yc[(ybase + (k0 + kk) * d) * 512 + t];
        }
        __syncthreads();
        if (w < kc) {
            #pragma unroll
            for (int i = 0; i < 16; i++) {
                float2 wv2 = ycs[w * 512 + i * 32 + lane];
                u64 wv  = pk(wv2.x, wv2.y);
                u64 wsw = pk(wv2.y, wv2.x);
                #pragma unroll
                for (int b2 = 0; b2 < 4; b2++) {
                    ulonglong2 x1 = *(const ulonglong2*)&xp1[w * 128 + i * 8 + b2 * 2];
                    ulonglong2 x2 = *(const ulonglong2*)&xp2[w * 128 + i * 8 + b2 * 2];
                    acc[b2*2]   = fma2(x1.x, wv,  acc[b2*2]);
                    acc[b2*2]   = fma2(x2.x, wsw, acc[b2*2]);
                    acc[b2*2+1] = fma2(x1.y, wv,  acc[b2*2+1]);
                    acc[b2*2+1] = fma2(x2.y, wsw, acc[b2*2+1]);
                }
            }
        }
    }
    __syncthreads();
    #pragma unroll
    for (int b = 0; b < 8; b++) red[(w * 32 + lane) * 8 + b] = acc[b];
    __syncthreads();
    for (int t = tid; t < 256; t += 128) {
        int o = t & 31, b = t >> 5;
        float sx = 0.0f, sy = 0.0f;
        #pragma unroll
        for (int ww = 0; ww < 4; ww++) {
            float lo, hi; upk(red[(ww * 32 + o) * 8 + b], lo, hi);
            sx += lo; sy += hi;
        }
        g_zc[s * 256 + b * 32 + o] = make_float2(sx, sy);
    }
}

// ---------------- l-reduction with Wsy (unchanged) ----------------
__global__ void k_zsum() {
    int mi = blockIdx.x / 31, ni = blockIdx.x % 31;
    int m = mi - 15, n = ni - 15;
    int am = m < 0 ? -m : m, an = n < 0 ? -n : n;
    int lmin = am > an ? am : an;
    int nl = 16 - lmin;
    __shared__ float ws[16 * 32];
    __shared__ int srow[16];
    int tid = threadIdx.x;
    if (tid < nl) {
        int l = lmin + tid;
        srow[tid] = c_OFF[l] + (m + l) * (2*l + 1) + (n + l);
    }
    __syncthreads();
    for (int idx = tid; idx < nl * 32; idx += 256) {
        int li = idx >> 5, j = idx & 31;
        ws[idx] = g_Wsy[srow[li] * 32 + j];
    }
    __syncthreads();
    float2 acc[32];
    #pragma unroll
    for (int j = 0; j < 32; j++) acc[j] = make_float2(0.0f, 0.0f);
    for (int li = 0; li < nl; li++) {
        float2 z = g_zc[srow[li] * 256 + tid];
        #pragma unroll
        for (int j = 0; j < 32; j++) {
            float w = ws[li * 32 + j];
            acc[j].x += z.x * w;
            acc[j].y += z.y * w;
        }
    }
    int base = (mi * 31 + ni) * 8192 + tid;
    #pragma unroll
    for (int j = 0; j < 32; j++)
        g_Zsum[base + j * 256] = acc[j];
}

// ---------------- inverse DFT over m-axis: m-pair fold + a-fold ----------------
// block per (ni, j, half): 1984 blocks x 128 threads
__global__ void k_g1() {
    int bid = blockIdx.x;
    int half = bid & 1;
    int j = (bid >> 1) & 31;
    int ni = bid >> 6;
    __shared__ __align__(16) float2 zin[31 * 128];
    __shared__ u64 twC2[16 * 16];   // [a 0..15][m 0..15] = (cos, cos)
    __shared__ u64 twS2[16 * 16];
    int tid = threadIdx.x;
    for (int idx = tid; idx < 31 * 128; idx += 128)
        zin[idx] = g_Zsum[((idx >> 7) * 31 + ni) * 8192 + j * 256 + half * 128 + (idx & 127)];
    for (int idx = tid; idx < 256; idx += 128) {
        int a = idx >> 4, mm = idx & 15;
        float sv, cv; sincosf(0.1963495408f * (float)(a * mm), &sv, &cv);  // pi/16
        twC2[idx] = pk(cv, cv);
        twS2[idx] = pk(sv, sv);
    }
    __syncthreads();
    u64 neg1 = pk(-1.0f, -1.0f);
    u64 one1 = pk(1.0f, 1.0f);
    u64 z0 = *(const u64*)&zin[15 * 128 + tid];
    u64 acc[32];
    #pragma unroll
    for (int a = 0; a < 32; a++) acc[a] = z0;
    for (int mm = 1; mm <= 15; mm++) {
        u64 zp = *(const u64*)&zin[(15 + mm) * 128 + tid];
        u64 zm = *(const u64*)&zin[(15 - mm) * 128 + tid];
        u64 U = add2(zp, zm);
        u64 V = fma2(zm, neg1, zp);            // zp - zm
        float vx, vy; upk(V, vx, vy);
        u64 iV = pk(-vy, vx);
        u64 sg = (mm & 1) ? neg1 : one1;
        #pragma unroll
        for (int a = 0; a < 16; a++) {
            u64 p = fma2(twC2[a * 16 + mm], U, fma2(twS2[a * 16 + mm], iV, 0ULL));
            acc[a]      = add2(acc[a], p);
            acc[a + 16] = fma2(p, sg, acc[a + 16]);
        }
    }
    #pragma unroll
    for (int a = 0; a < 32; a++) {
        float lo, hi; upk(acc[a], lo, hi);
        g_U1[((a * 31 + ni) * 32 + j) * 256 + half * 128 + tid] = make_float2(lo, hi);
    }
}

// ---------------- inverse DFT over n-axis, real part, + bias: n-pair fold + c-fold ----------------
// block per (a, j, half): 2048 blocks x 128 threads
__global__ void k_g2(const float* __restrict__ bias, float* __restrict__ out) {
    int bid = blockIdx.x;
    int half = bid & 1;
    int j = (bid >> 1) & 31;
    int a = bid >> 6;
    __shared__ __align__(16) float2 uin[31 * 128];
    __shared__ u64 twA[16 * 8];   // [n][q]: (cos(2q n pi/16), cos((2q+1) n pi/16))
    __shared__ u64 twB[16 * 8];   // sines
    int tid = threadIdx.x;
    for (int idx = tid; idx < 31 * 128; idx += 128)
        uin[idx] = g_U1[((a * 31 + (idx >> 7)) * 32 + j) * 256 + half * 128 + (idx & 127)];
    for (int idx = tid; idx < 128; idx += 128) { }
    if (tid < 128) {
        int n = tid >> 3, q = tid & 7;
        float s0, c0v, s1, c1v;
        sincosf(0.1963495408f * (float)(2 * q * n), &s0, &c0v);
        sincosf(0.1963495408f * (float)((2 * q + 1) * n), &s1, &c1v);
        twA[tid] = pk(c0v, c1v);
        twB[tid] = pk(s0, s1);
    }
    __syncthreads();
    u64 neg1 = pk(-1.0f, -1.0f);
    u64 one1 = pk(1.0f, 1.0f);
    int bo = half * 128 + tid;
    float bv = bias[bo & 31];
    float2 u0 = uin[15 * 128 + tid];
    float base = bv + u0.x;
    u64 v2[16];
    #pragma unroll
    for (int q = 0; q < 16; q++) v2[q] = pk(base, base);
    for (int nn = 1; nn <= 15; nn++) {
        float2 up = uin[(15 + nn) * 128 + tid];
        float2 um = uin[(15 - nn) * 128 + tid];
        float Uv = up.x + um.x;
        float Vv = um.y - up.y;
        u64 U2 = pk(Uv, Uv), V2 = pk(Vv, Vv);
        u64 sg = (nn & 1) ? neg1 : one1;
        #pragma unroll
        for (int q = 0; q < 8; q++) {
            u64 p = fma2(twA[nn * 8 + q], U2, fma2(twB[nn * 8 + q], V2, 0ULL));
            v2[q]     = add2(v2[q], p);
            v2[q + 8] = fma2(p, sg, v2[q + 8]);
        }
    }
    float v[32];
    #pragma unroll
    for (int q = 0; q < 8; q++) {
        upk(v2[q], v[2*q], v[2*q + 1]);          // c = 0..15
        upk(v2[q + 8], v[16 + 2*q], v[17 + 2*q]); // c = 16..31
    }
    float4* op = (float4*)(out + (long)bo * 32768 + a * 1024 + j * 32);
    #pragma unroll
    for (int q2 = 0; q2 < 8; q2++)
        op[q2] = make_float4(v[4*q2], v[4*q2+1], v[4*q2+2], v[4*q2+3]);
}

// ---------------- launch ----------------
extern "C" void kernel_launch(void* const* d_in, const int* in_sizes, int n_in,
                              void* d_out, int out_size) {
    const float* x    = (const float*)d_in[0];   // [8,16,64,64,64]
    const float* ker  = (const float*)d_in[1];   // [16,32,72]
    const float* bias = (const float*)d_in[2];   // [32]
    const float* ge   = (const float*)d_in[3];   // [72,3]
    float* out = (float*)d_out;                  // [8,32,32,32,32]

    k_init  <<<144, 256>>>(ker);
    k_wigner<<<NSPEC, 192>>>(ge);
    k_dftA  <<<8192, 256>>>(x);
    k_dftC  <<<3968, 256>>>();
    k_xc    <<<NSPEC, 128>>>();
    k_yc    <<<1364, 512>>>();
    k_ze    <<<NSPEC, 128>>>();
    k_zsum  <<<961, 256>>>();
    k_g1    <<<1984, 128>>>();
    k_g2    <<<2048, 128>>>(bias, out);
}

// round 9
// speedup vs baseline: 2.1193x; 1.0973x over previous
#include <cuda_runtime.h>
#include <cuda_bf16.h>
#include <math.h>

// ---------------- constants ----------------
#define NSPEC 5456
#define PI_F 3.14159265358979323846f

__constant__ int c_OFF[17] = {0,1,10,35,84,165,286,455,680,969,1330,1771,2300,2925,3654,4495,5456};

typedef unsigned long long u64;

// ---------------- f32x2 packed helpers ----------------
__device__ __forceinline__ u64 pk(float lo, float hi) {
    u64 r; asm("mov.b64 %0,{%1,%2};" : "=l"(r) : "f"(lo), "f"(hi)); return r;
}
__device__ __forceinline__ u64 fma2(u64 a, u64 b, u64 c) {
    u64 r; asm("fma.rn.f32x2 %0,%1,%2,%3;" : "=l"(r) : "l"(a), "l"(b), "l"(c)); return r;
}
__device__ __forceinline__ u64 add2(u64 a, u64 b) {
    u64 r; asm("add.rn.f32x2 %0,%1,%2;" : "=l"(r) : "l"(a), "l"(b)); return r;
}
__device__ __forceinline__ void upk(u64 v, float& lo, float& hi) {
    asm("mov.b64 {%0,%1},%2;" : "=f"(lo), "=f"(hi) : "l"(v));
}

// ---------------- scratch (static device globals; no allocation) ----------------
__device__ float2 g_T1[8388608];     // [bf=128][m=16][j=64][c=64]   (m >= 0 only)
__device__ float2 g_T2[7872512];     // [mi=31][ni=31][j=64][bf=128]   (NEW layout)
__device__ float  g_Wan[NSPEC*64];
__device__ float  g_Wsy[NSPEC*32];
__device__ float2 g_D[NSPEC*72];
__device__ float  g_wquad[64];
__device__ float  g_KT[72*512];
__device__ float2 g_xc[NSPEC*128];   // [s][b*16+f]
__device__ float2 g_yc[NSPEC*512];   // [s][i*32+o]
__device__ float2 g_zc[NSPEC*256];   // [s][b*32+o]
__device__ float2 g_Zsum[7872512];   // [mi=31][ni=31][j=32][bo=256]
__device__ float2 g_U1[8126464];     // [a=32][ni=31][j=32][bo=256]

// ---------------- init ----------------
__global__ void k_init(const float* __restrict__ ker) {
    int idx = blockIdx.x * blockDim.x + threadIdx.x;
    if (idx < 36864) {
        int g  = idx >> 9;
        int io = idx & 511;
        g_KT[idx] = ker[io * 72 + g] * (1.0f / 12.0f);
    }
    if (idx < 64) {
        int j = idx;
        float inner = 0.0f;
        for (int k = 0; k < 32; k++)
            inner += sinf((float)((2*j+1)*(2*k+1)) * PI_F / 128.0f) / (float)(2*k+1);
        float w = (2.0f / 32.0f) * sinf(PI_F * (float)(2*j+1) / 128.0f) * inner;
        g_wquad[j] = w / 4096.0f;
    }
}

// ---------------- Wigner tables ----------------
__global__ void k_wigner(const float* __restrict__ ge) {
    int s = blockIdx.x;
    __shared__ float lcoef[32];
    __shared__ int shp[5];
    if (threadIdx.x == 0) {
        int l = 0; while (c_OFF[l+1] <= s) l++;
        int dsz = 2*l + 1;
        int rem = s - c_OFF[l];
        int M = rem / dsz - l;
        int N = rem % dsz - l;
        int Kmin = (M - N) > 0 ? (M - N) : 0;
        int Kmax = (l + M) < (l - N) ? (l + M) : (l - N);
        double lf[32];
        lf[0] = 0.0;
        for (int i = 1; i < 32; i++) lf[i] = lf[i-1] + log((double)i);
        double lgA = 0.5 * (lf[l+M] + lf[l-M] + lf[l+N] + lf[l-N]);
        for (int K = Kmin; K <= Kmax; K++)
            lcoef[K] = (float)(lgA - (lf[K] + lf[l+M-K] + lf[l-N-K] + lf[N-M+K]));
        shp[0] = l; shp[1] = M; shp[2] = N; shp[3] = Kmin; shp[4] = Kmax;
    }
    __syncthreads();
    int t = threadIdx.x;
    if (t >= 168) return;
    int l = shp[0], M = shp[1], N = shp[2], Kmin = shp[3], Kmax = shp[4];
    float beta;
    if (t < 64)       beta = PI_F * (float)(2*t + 1) / 128.0f;
    else if (t < 96)  beta = PI_F * (float)(2*(t-64) + 1) / 64.0f;
    else              beta = ge[(t - 96) * 3 + 1];
    float ch  = cosf(0.5f * beta);
    float shv = sinf(0.5f * beta);
    float lc  = logf(ch);
    float lsn = logf(shv);
    float dval = 0.0f;
    for (int K = Kmin; K <= Kmax; K++) {
        int e1 = 2*l + M - N - 2*K;
        int e2 = N - M + 2*K;
        float arg = lcoef[K];
        if (e1) arg += (float)e1 * lc;
        if (e2) arg += (float)e2 * lsn;
        float term = expf(arg);
        dval += (K & 1) ? -term : term;
    }
    if (t < 64) {
        g_Wan[s * 64 + t] = dval * g_wquad[t];
    } else if (t < 96) {
        g_Wsy[s * 32 + (t - 64)] = dval * (float)(2*l + 1);
    } else {
        int g = t - 96;
        float alpha = ge[g*3 + 0], gamma = ge[g*3 + 2];
        float th = (float)M * alpha + (float)N * gamma;
        float sv, cv; sincosf(th, &sv, &cv);
        g_D[s * 72 + g] = make_float2(dval * cv, -dval * sv);
    }
}

// ---------------- Stage A: DFT over first axis, a-folded ----------------
// block per (bf, j): 8192 blocks x 256 threads = (c 0..63) x (m0 0..3)
__global__ void k_dftA(const float* __restrict__ x) {
    __shared__ __align__(16) float sxu[64 * 36];
    __shared__ __align__(16) float sxv[64 * 36];
    __shared__ __align__(16) float twC[16 * 32];
    __shared__ __align__(16) float twS[16 * 32];
    int bid = blockIdx.x;
    int j = bid & 63, bf = bid >> 6;
    int tid = threadIdx.x;
    const float* xb = x + bf * 262144 + j * 64;
    for (int idx = tid; idx < 2048; idx += 256) {
        int a = idx >> 6, c = idx & 63;
        float xa = xb[a * 4096 + c];
        float xc2 = xb[(a + 32) * 4096 + c];
        sxu[c * 36 + a] = xa + xc2;
        sxv[c * 36 + a] = xa - xc2;
    }
    for (int idx = tid; idx < 512; idx += 256) {
        int m = idx >> 5, a = idx & 31;
        float sv, cv; sincosf(0.0981747704f * (float)(a * m), &sv, &cv);
        twC[idx] = cv; twS[idx] = sv;
    }
    __syncthreads();
    int c = tid & 63, m0 = tid >> 6;
    u64 aC[4] = {0ULL,0ULL,0ULL,0ULL}, aS[4] = {0ULL,0ULL,0ULL,0ULL};
    for (int a0 = 0; a0 < 32; a0 += 4) {
        ulonglong2 U = *(const ulonglong2*)&sxu[c * 36 + a0];
        ulonglong2 V = *(const ulonglong2*)&sxv[c * 36 + a0];
        #pragma unroll
        for (int it = 0; it < 4; it++) {
            int m = m0 * 4 + it;
            ulonglong2 TC = *(const ulonglong2*)&twC[m * 32 + a0];
            ulonglong2 TS = *(const ulonglong2*)&twS[m * 32 + a0];
            u64 xlo = (it & 1) ? V.x : U.x;
            u64 xhi = (it & 1) ? V.y : U.y;
            aC[it] = fma2(xlo, TC.x, aC[it]);
            aC[it] = fma2(xhi, TC.y, aC[it]);
            aS[it] = fma2(xlo, TS.x, aS[it]);
            aS[it] = fma2(xhi, TS.y, aS[it]);
        }
    }
    #pragma unroll
    for (int it = 0; it < 4; it++) {
        int m = m0 * 4 + it;
        float c1, c2, s1, s2;
        upk(aC[it], c1, c2); upk(aS[it], s1, s2);
        g_T1[bf * 65536 + m * 4096 + j * 64 + c] = make_float2(c1 + c2, -(s1 + s2));
    }
}

// ---------------- Stage C: DFT over third axis; NEW T2 layout [mi][ni][j][bf] ----------------
// grid: mi*128 + j*2 + bfh = 3968 blocks x 256 threads = (bfl 0..63) x (q0 0..3)
__global__ void k_dftC() {
    __shared__ __align__(16) float suX[64 * 36];
    __shared__ __align__(16) float suY[64 * 36];
    __shared__ __align__(16) float svX[64 * 36];
    __shared__ __align__(16) float svY[64 * 36];
    __shared__ __align__(16) float twQC[16 * 32];
    __shared__ __align__(16) float twQS[16 * 32];
    int bid = blockIdx.x;
    int mi  = bid >> 7;
    int j   = (bid >> 1) & 63;
    int bf0 = (bid & 1) * 64;
    int m = mi - 15;
    int am = m < 0 ? -m : m;
    float sgn = (m < 0) ? -1.0f : 1.0f;
    int tid = threadIdx.x;
    for (int idx = tid; idx < 2048; idx += 256) {
        int bfl = idx >> 5, c = idx & 31;
        const float2* p = &g_T1[(bf0 + bfl) * 65536 + am * 4096 + j * 64];
        float2 a = p[c];
        float2 b = p[c + 32];
        suX[bfl * 36 + c] = a.x + b.x;
        svX[bfl * 36 + c] = a.x - b.x;
        suY[bfl * 36 + c] = sgn * (a.y + b.y);
        svY[bfl * 36 + c] = sgn * (a.y - b.y);
    }
    for (int idx = tid; idx < 512; idx += 256) {
        int q = idx >> 5, c = idx & 31;
        float sv, cv; sincosf(0.0981747704f * (float)(q * c), &sv, &cv);
        twQC[idx] = cv; twQS[idx] = sv;
    }
    __syncthreads();
    int bfl = tid & 63, q0 = tid >> 6;
    const float* sX = (q0 & 1) ? svX : suX;
    const float* sY = (q0 & 1) ? svY : suY;
    u64 A[16];
    #pragma unroll
    for (int i = 0; i < 16; i++) A[i] = 0ULL;
    for (int c0 = 0; c0 < 32; c0 += 4) {
        ulonglong2 X = *(const ulonglong2*)&sX[bfl * 36 + c0];
        ulonglong2 Y = *(const ulonglong2*)&sY[bfl * 36 + c0];
        #pragma unroll
        for (int it = 0; it < 4; it++) {
            int q = q0 + 4 * it;
            ulonglong2 TC = *(const ulonglong2*)&twQC[q * 32 + c0];
            ulonglong2 TS = *(const ulonglong2*)&twQS[q * 32 + c0];
            A[it*4+0] = fma2(X.x, TC.x, A[it*4+0]);
            A[it*4+0] = fma2(X.y, TC.y, A[it*4+0]);
            A[it*4+1] = fma2(X.x, TS.x, A[it*4+1]);
            A[it*4+1] = fma2(X.y, TS.y, A[it*4+1]);
            A[it*4+2] = fma2(Y.x, TC.x, A[it*4+2]);
            A[it*4+2] = fma2(Y.y, TC.y, A[it*4+2]);
            A[it*4+3] = fma2(Y.x, TS.x, A[it*4+3]);
            A[it*4+3] = fma2(Y.y, TS.y, A[it*4+3]);
        }
    }
    #pragma unroll
    for (int it = 0; it < 4; it++) {
        int q = q0 + 4 * it;
        float a1, a2;
        float Sxc, SxS, Syc, SyS;
        upk(A[it*4+0], a1, a2); Sxc = a1 + a2;
        upk(A[it*4+1], a1, a2); SxS = a1 + a2;
        upk(A[it*4+2], a1, a2); Syc = a1 + a2;
        upk(A[it*4+3], a1, a2); SyS = a1 + a2;
        g_T2[((mi * 31 + (15 + q)) * 64 + j) * 128 + bf0 + bfl] =
            make_float2(Sxc + SyS, Syc - SxS);
        if (q > 0)
            g_T2[((mi * 31 + (15 - q)) * 64 + j) * 128 + bf0 + bfl] =
                make_float2(Sxc - SyS, Syc + SxS);
    }
}

// ---------------- xc: block per (mi,ni), coalesced single pass over T2 ----------------
// grid 961 blocks x 128 threads (bf)
__global__ void k_xc() {
    int mi = blockIdx.x / 31, ni = blockIdx.x % 31;
    int m = mi - 15, n = ni - 15;
    int am = m < 0 ? -m : m, an = n < 0 ? -n : n;
    int lmin = am > an ? am : an;
    int nl = 16 - lmin;
    __shared__ float ws[16 * 64];
    __shared__ int srow[16];
    int tid = threadIdx.x;
    if (tid < nl) {
        int l = lmin + tid;
        srow[tid] = c_OFF[l] + (m + l) * (2*l + 1) + (n + l);
    }
    __syncthreads();
    for (int idx = tid; idx < nl * 64; idx += 128)
        ws[idx] = g_Wan[srow[idx >> 6] * 64 + (idx & 63)];
    __syncthreads();
    u64 acc[16];
    #pragma unroll
    for (int i = 0; i < 16; i++) acc[i] = 0ULL;
    const float2* src = &g_T2[(mi * 31 + ni) * 8192 + tid];
    for (int j = 0; j < 64; j++) {
        float2 v = src[j * 128];
        u64 vp = pk(v.x, v.y);
        #pragma unroll
        for (int li = 0; li < 16; li++) {
            if (li < nl) {
                float w = ws[li * 64 + j];
                acc[li] = fma2(vp, pk(w, w), acc[li]);
            }
        }
    }
    #pragma unroll
    for (int li = 0; li < 16; li++) {
        if (li < nl) {
            float lo, hi; upk(acc[li], lo, hi);
            g_xc[srow[li] * 128 + tid] = make_float2(lo, hi);
        }
    }
}

// ---------------- yc: 4 spectral rows per block ----------------
__global__ void k_yc() {
    int s4 = blockIdx.x * 4;
    __shared__ __align__(16) float2 ds[4 * 72];
    int t = threadIdx.x;
    if (t < 288) ds[t] = g_D[s4 * 72 + t];
    __syncthreads();
    u64 a0 = 0ULL, a1 = 0ULL, a2 = 0ULL, a3 = 0ULL;
    #pragma unroll 4
    for (int g = 0; g < 72; g++) {
        float k = g_KT[g * 512 + t];
        u64 k2 = pk(k, k);
        a0 = fma2(k2, *(const u64*)&ds[g],       a0);
        a1 = fma2(k2, *(const u64*)&ds[72 + g],  a1);
        a2 = fma2(k2, *(const u64*)&ds[144 + g], a2);
        a3 = fma2(k2, *(const u64*)&ds[216 + g], a3);
    }
    float lo, hi;
    upk(a0, lo, hi); g_yc[(s4 + 0) * 512 + t] = make_float2(lo, hi);
    upk(a1, lo, hi); g_yc[(s4 + 1) * 512 + t] = make_float2(lo, hi);
    upk(a2, lo, hi); g_yc[(s4 + 2) * 512 + t] = make_float2(lo, hi);
    upk(a3, lo, hi); g_yc[(s4 + 3) * 512 + t] = make_float2(lo, hi);
}

// ---------------- main block-diagonal complex GEMM: no reduction, 2 outputs/thread ----------------
// block per s: 5456 blocks x 128 threads; thread = (b = tid>>4, o-pair = tid&15)
__global__ void k_ze() {
    __shared__ ulonglong2 xpi[8 * 128];   // 16KB: [kk][i*8+b] = {(xr,xr), (-xi,xi)}
    __shared__ float2     ycs[8 * 512];   // 32KB: [kk][i*32+o]
    int s = blockIdx.x;
    int tid = threadIdx.x;
    int b = tid >> 4, o2 = tid & 15;
    int l = 0;
    #pragma unroll
    for (int i = 1; i < 16; i++) l += (c_OFF[i] <= s) ? 1 : 0;
    int d = 2 * l + 1;
    int rem = s - c_OFF[l];
    int xbase = c_OFF[l] + (rem / d) * d;
    int ybase = c_OFF[l] + (rem % d);
    u64 acc0 = 0ULL, acc1 = 0ULL;
    for (int k0 = 0; k0 < d; k0 += 8) {
        int kc = d - k0; if (kc > 8) kc = 8;
        if (k0) __syncthreads();
        for (int idx = tid; idx < kc * 128; idx += 128) {
            int kk = idx >> 7;
            int i  = (idx >> 3) & 15;
            int bb = idx & 7;
            float2 v = g_xc[(xbase + k0 + kk) * 128 + bb * 16 + i];
            xpi[kk * 128 + i * 8 + bb] = make_ulonglong2(pk(v.x, v.x), pk(-v.y, v.y));
        }
        for (int idx = tid; idx < kc * 256; idx += 128) {
            int kk = idx >> 8, t = idx & 255;
            float4 vv = ((const float4*)&g_yc[(ybase + (k0 + kk) * d) * 512])[t];
            *(float4*)&ycs[kk * 512 + t * 2] = vv;
        }
        __syncthreads();
        for (int kk = 0; kk < kc; kk++) {
            const ulonglong2* xr = &xpi[kk * 128 + b];
            const float2*     yr = &ycs[kk * 512 + o2 * 2];
            #pragma unroll
            for (int i = 0; i < 16; i++) {
                ulonglong2 X = xr[i * 8];
                ulonglong2 Y = *(const ulonglong2*)&yr[i * 32];
                float y0r, y0i, y1r, y1i;
                upk(Y.x, y0r, y0i); upk(Y.y, y1r, y1i);
                acc0 = fma2(X.x, Y.x, acc0);
                acc0 = fma2(X.y, pk(y0i, y0r), acc0);
                acc1 = fma2(X.x, Y.y, acc1);
                acc1 = fma2(X.y, pk(y1i, y1r), acc1);
            }
        }
    }
    float a0r, a0i, a1r, a1i;
    upk(acc0, a0r, a0i); upk(acc1, a1r, a1i);
    *(float4*)&g_zc[s * 256 + b * 32 + o2 * 2] = make_float4(a0r, a0i, a1r, a1i);
}

// ---------------- l-reduction with Wsy ----------------
__global__ void k_zsum() {
    int mi = blockIdx.x / 31, ni = blockIdx.x % 31;
    int m = mi - 15, n = ni - 15;
    int am = m < 0 ? -m : m, an = n < 0 ? -n : n;
    int lmin = am > an ? am : an;
    int nl = 16 - lmin;
    __shared__ float ws[16 * 32];
    __shared__ int srow[16];
    int tid = threadIdx.x;
    if (tid < nl) {
        int l = lmin + tid;
        srow[tid] = c_OFF[l] + (m + l) * (2*l + 1) + (n + l);
    }
    __syncthreads();
    for (int idx = tid; idx < nl * 32; idx += 256) {
        int li = idx >> 5, j = idx & 31;
        ws[idx] = g_Wsy[srow[li] * 32 + j];
    }
    __syncthreads();
    float2 acc[32];
    #pragma unroll
    for (int j = 0; j < 32; j++) acc[j] = make_float2(0.0f, 0.0f);
    for (int li = 0; li < nl; li++) {
        float2 z = g_zc[srow[li] * 256 + tid];
        #pragma unroll
        for (int j = 0; j < 32; j++) {
            float w = ws[li * 32 + j];
            acc[j].x += z.x * w;
            acc[j].y += z.y * w;
        }
    }
    int base = (mi * 31 + ni) * 8192 + tid;
    #pragma unroll
    for (int j = 0; j < 32; j++)
        g_Zsum[base + j * 256] = acc[j];
}

// ---------------- inverse DFT over m-axis: m-pair fold + a-fold ----------------
__global__ void k_g1() {
    int bid = blockIdx.x;
    int half = bid & 1;
    int j = (bid >> 1) & 31;
    int ni = bid >> 6;
    __shared__ __align__(16) float2 zin[31 * 128];
    __shared__ u64 twC2[16 * 16];
    __shared__ u64 twS2[16 * 16];
    int tid = threadIdx.x;
    for (int idx = tid; idx < 31 * 128; idx += 128)
        zin[idx] = g_Zsum[((idx >> 7) * 31 + ni) * 8192 + j * 256 + half * 128 + (idx & 127)];
    for (int idx = tid; idx < 256; idx += 128) {
        int a = idx >> 4, mm = idx & 15;
        float sv, cv; sincosf(0.1963495408f * (float)(a * mm), &sv, &cv);
        twC2[idx] = pk(cv, cv);
        twS2[idx] = pk(sv, sv);
    }
    __syncthreads();
    u64 neg1 = pk(-1.0f, -1.0f);
    u64 one1 = pk(1.0f, 1.0f);
    u64 z0 = *(const u64*)&zin[15 * 128 + tid];
    u64 acc[32];
    #pragma unroll
    for (int a = 0; a < 32; a++) acc[a] = z0;
    for (int mm = 1; mm <= 15; mm++) {
        u64 zp = *(const u64*)&zin[(15 + mm) * 128 + tid];
        u64 zm = *(const u64*)&zin[(15 - mm) * 128 + tid];
        u64 U = add2(zp, zm);
        u64 V = fma2(zm, neg1, zp);
        float vx, vy; upk(V, vx, vy);
        u64 iV = pk(-vy, vx);
        u64 sg = (mm & 1) ? neg1 : one1;
        #pragma unroll
        for (int a = 0; a < 16; a++) {
            u64 p = fma2(twC2[a * 16 + mm], U, fma2(twS2[a * 16 + mm], iV, 0ULL));
            acc[a]      = add2(acc[a], p);
            acc[a + 16] = fma2(p, sg, acc[a + 16]);
        }
    }
    #pragma unroll
    for (int a = 0; a < 32; a++) {
        float lo, hi; upk(acc[a], lo, hi);
        g_U1[((a * 31 + ni) * 32 + j) * 256 + half * 128 + tid] = make_float2(lo, hi);
    }
}

// ---------------- inverse DFT over n-axis, real part, + bias ----------------
__global__ void k_g2(const float* __restrict__ bias, float* __restrict__ out) {
    int bid = blockIdx.x;
    int half = bid & 1;
    int j = (bid >> 1) & 31;
    int a = bid >> 6;
    __shared__ __align__(16) float2 uin[31 * 128];
    __shared__ u64 twA[16 * 8];
    __shared__ u64 twB[16 * 8];
    int tid = threadIdx.x;
    for (int idx = tid; idx < 31 * 128; idx += 128)
        uin[idx] = g_U1[((a * 31 + (idx >> 7)) * 32 + j) * 256 + half * 128 + (idx & 127)];
    if (tid < 128) {
        int n = tid >> 3, q = tid & 7;
        float s0, c0v, s1, c1v;
        sincosf(0.1963495408f * (float)(2 * q * n), &s0, &c0v);
        sincosf(0.1963495408f * (float)((2 * q + 1) * n), &s1, &c1v);
        twA[tid] = pk(c0v, c1v);
        twB[tid] = pk(s0, s1);
    }
    __syncthreads();
    u64 neg1 = pk(-1.0f, -1.0f);
    u64 one1 = pk(1.0f, 1.0f);
    int bo = half * 128 + tid;
    float bv = bias[bo & 31];
    float2 u0 = uin[15 * 128 + tid];
    float base = bv + u0.x;
    u64 v2[16];
    #pragma unroll
    for (int q = 0; q < 16; q++) v2[q] = pk(base, base);
    for (int nn = 1; nn <= 15; nn++) {
        float2 up = uin[(15 + nn) * 128 + tid];
        float2 um = uin[(15 - nn) * 128 + tid];
        float Uv = up.x + um.x;
        float Vv = um.y - up.y;
        u64 U2 = pk(Uv, Uv), V2 = pk(Vv, Vv);
        u64 sg = (nn & 1) ? neg1 : one1;
        #pragma unroll
        for (int q = 0; q < 8; q++) {
            u64 p = fma2(twA[nn * 8 + q], U2, fma2(twB[nn * 8 + q], V2, 0ULL));
            v2[q]     = add2(v2[q], p);
            v2[q + 8] = fma2(p, sg, v2[q + 8]);
        }
    }
    float v[32];
    #pragma unroll
    for (int q = 0; q < 8; q++) {
        upk(v2[q], v[2*q], v[2*q + 1]);
        upk(v2[q + 8], v[16 + 2*q], v[17 + 2*q]);
    }
    float4* op = (float4*)(out + (long)bo * 32768 + a * 1024 + j * 32);
    #pragma unroll
    for (int q2 = 0; q2 < 8; q2++)
        op[q2] = make_float4(v[4*q2], v[4*q2+1], v[4*q2+2], v[4*q2+3]);
}

// ---------------- launch ----------------
extern "C" void kernel_launch(void* const* d_in, const int* in_sizes, int n_in,
                              void* d_out, int out_size) {
    const float* x    = (const float*)d_in[0];   // [8,16,64,64,64]
    const float* ker  = (const float*)d_in[1];   // [16,32,72]
    const float* bias = (const float*)d_in[2];   // [32]
    const float* ge   = (const float*)d_in[3];   // [72,3]
    float* out = (float*)d_out;                  // [8,32,32,32,32]

    k_init  <<<144, 256>>>(ker);
    k_wigner<<<NSPEC, 192>>>(ge);
    k_dftA  <<<8192, 256>>>(x);
    k_dftC  <<<3968, 256>>>();
    k_xc    <<<961, 128>>>();
    k_yc    <<<1364, 512>>>();
    k_ze    <<<NSPEC, 128>>>();
    k_zsum  <<<961, 256>>>();
    k_g1    <<<1984, 128>>>();
    k_g2    <<<2048, 128>>>(bias, out);
}